// round 1
// baseline (speedup 1.0000x reference)
#include <cuda_runtime.h>
#include <math_constants.h>

// TopKTokenChoiceRouter: tokens(8192,4096) fp32 @ W^T(4096,64) -> softmax(64) -> top2
// Output layout assumed: [weights (M*2 floats)] then [indices cast to float (M*2)],
// guarded by out_size.

#define K_DIM 4096
#define NE    64     // experts
#define MT    64     // tokens per block
#define KC    32     // K chunk
#define SPAD  68     // smem row stride (keeps float4 alignment, spreads banks)

__global__ __launch_bounds__(256) void router_kernel(
    const float* __restrict__ x, const float* __restrict__ W,
    float* __restrict__ out, int M, int write_idx)
{
    __shared__ float xs[2][KC][SPAD];   // xs[buf][k][token]  (transposed tile)
    __shared__ float ws[2][KC][SPAD];   // ws[buf][k][expert]

    const int tid    = threadIdx.x;
    const int m_base = blockIdx.x * MT;
    const int tx = tid & 15;            // expert direction (16 threads)
    const int ty = tid >> 4;            // token direction (16 threads)
    const int m0 = ty * 4;
    const int n0 = tx * 4;

    float acc[4][4];
    #pragma unroll
    for (int i = 0; i < 4; i++)
        #pragma unroll
        for (int j = 0; j < 4; j++) acc[i][j] = 0.f;

    // Load assignment: 64 rows x 8 float4 per tile = 512 float4; 2 per thread.
    const int r0 = tid >> 3;            // 0..31
    const int v0 = tid & 7;             // 0..7 (float4 index within 32-float chunk)
    const int r1 = r0 + 32;

    const float* gx0 = x + (size_t)(m_base + r0) * K_DIM + v0 * 4;
    const float* gx1 = x + (size_t)(m_base + r1) * K_DIM + v0 * 4;
    const float* gw0 = W + (size_t)r0 * K_DIM + v0 * 4;
    const float* gw1 = W + (size_t)r1 * K_DIM + v0 * 4;

    // Preload chunk 0 into registers
    float4 ax0 = *(const float4*)(gx0);
    float4 ax1 = *(const float4*)(gx1);
    float4 aw0 = *(const float4*)(gw0);
    float4 aw1 = *(const float4*)(gw1);

    // Store stage 0
    {
        const int kc = v0 * 4;
        xs[0][kc+0][r0] = ax0.x; xs[0][kc+1][r0] = ax0.y; xs[0][kc+2][r0] = ax0.z; xs[0][kc+3][r0] = ax0.w;
        xs[0][kc+0][r1] = ax1.x; xs[0][kc+1][r1] = ax1.y; xs[0][kc+2][r1] = ax1.z; xs[0][kc+3][r1] = ax1.w;
        ws[0][kc+0][r0] = aw0.x; ws[0][kc+1][r0] = aw0.y; ws[0][kc+2][r0] = aw0.z; ws[0][kc+3][r0] = aw0.w;
        ws[0][kc+0][r1] = aw1.x; ws[0][kc+1][r1] = aw1.y; ws[0][kc+2][r1] = aw1.z; ws[0][kc+3][r1] = aw1.w;
    }
    __syncthreads();

    int buf = 0;
    for (int kb = 0; kb < K_DIM; kb += KC) {
        const bool has_next = (kb + KC) < K_DIM;
        if (has_next) {
            const int off = kb + KC;
            ax0 = *(const float4*)(gx0 + off);
            ax1 = *(const float4*)(gx1 + off);
            aw0 = *(const float4*)(gw0 + off);
            aw1 = *(const float4*)(gw1 + off);
        }

        #pragma unroll
        for (int k = 0; k < KC; ++k) {
            float4 a = *(const float4*)&xs[buf][k][m0];
            float4 b = *(const float4*)&ws[buf][k][n0];
            acc[0][0] += a.x * b.x; acc[0][1] += a.x * b.y; acc[0][2] += a.x * b.z; acc[0][3] += a.x * b.w;
            acc[1][0] += a.y * b.x; acc[1][1] += a.y * b.y; acc[1][2] += a.y * b.z; acc[1][3] += a.y * b.w;
            acc[2][0] += a.z * b.x; acc[2][1] += a.z * b.y; acc[2][2] += a.z * b.z; acc[2][3] += a.z * b.w;
            acc[3][0] += a.w * b.x; acc[3][1] += a.w * b.y; acc[3][2] += a.w * b.z; acc[3][3] += a.w * b.w;
        }

        if (has_next) {
            __syncthreads();   // everyone done reading buf^1 (it was consumed last iter)
            const int nb = buf ^ 1;
            const int kc = v0 * 4;
            xs[nb][kc+0][r0] = ax0.x; xs[nb][kc+1][r0] = ax0.y; xs[nb][kc+2][r0] = ax0.z; xs[nb][kc+3][r0] = ax0.w;
            xs[nb][kc+0][r1] = ax1.x; xs[nb][kc+1][r1] = ax1.y; xs[nb][kc+2][r1] = ax1.z; xs[nb][kc+3][r1] = ax1.w;
            ws[nb][kc+0][r0] = aw0.x; ws[nb][kc+1][r0] = aw0.y; ws[nb][kc+2][r0] = aw0.z; ws[nb][kc+3][r0] = aw0.w;
            ws[nb][kc+0][r1] = aw1.x; ws[nb][kc+1][r1] = aw1.y; ws[nb][kc+2][r1] = aw1.z; ws[nb][kc+3][r1] = aw1.w;
            __syncthreads();
            buf = nb;
        }
    }

    // ---- Epilogue: logits -> smem (reuse xs: 2*KC*SPAD = 4352 floats = MT*SPAD) ----
    __syncthreads();
    float* logits = &xs[0][0][0];   // [MT][SPAD]
    #pragma unroll
    for (int i = 0; i < 4; i++)
        #pragma unroll
        for (int j = 0; j < 4; j++)
            logits[(m0 + i) * SPAD + (n0 + j)] = acc[i][j];
    __syncthreads();

    if (tid < MT) {
        const float* lr = logits + tid * SPAD;
        float v1 = -CUDART_INF_F, v2 = -CUDART_INF_F;
        int   i1 = 0, i2 = 0;
        #pragma unroll 8
        for (int e = 0; e < NE; ++e) {
            float l = lr[e];
            if (l > v1)      { v2 = v1; i2 = i1; v1 = l; i1 = e; }
            else if (l > v2) { v2 = l;  i2 = e; }
        }
        float denom = 0.f;
        #pragma unroll 8
        for (int e = 0; e < NE; ++e) denom += __expf(lr[e] - v1);
        const float inv = 1.0f / denom;
        const int gt = m_base + tid;
        out[gt * 2 + 0] = inv;                       // exp(v1-v1)/denom
        out[gt * 2 + 1] = __expf(v2 - v1) * inv;
        if (write_idx) {
            float* oi = out + 2 * M;
            oi[gt * 2 + 0] = (float)i1;
            oi[gt * 2 + 1] = (float)i2;
        }
    }
}

extern "C" void kernel_launch(void* const* d_in, const int* in_sizes, int n_in,
                              void* d_out, int out_size) {
    const float* x = (const float*)d_in[0];   // (2048,4,4096) fp32 -> 8192 x 4096
    const float* W = (const float*)d_in[1];   // (64,4096) fp32
    float* out = (float*)d_out;

    const int M = in_sizes[0] / K_DIM;        // 8192 tokens
    const int write_idx = (out_size >= 4 * M) ? 1 : 0;

    router_kernel<<<M / MT, 256>>>(x, W, out, M, write_idx);
}

// round 2
// speedup vs baseline: 1.7837x; 1.7837x over previous
#include <cuda_runtime.h>
#include <math_constants.h>

// TopKTokenChoiceRouter: x(8192,4096) fp32 @ W^T(4096,64) -> softmax(64) -> top2.
// Split-K GEMM (f32x2 packed FFMA) -> partials -> reduce + top2 + softmax kernel.
// Output layout: [weights (M*2 f32)][indices as f32 (M*2)] (validated in round 1).

#define K_DIM  4096
#define NE     64
#define BT     128            // tokens per block tile
#define KC     16             // k per smem chunk
#define NSPLIT 8
#define KSPLIT (K_DIM / NSPLIT)   // 512
#define XPAD   (BT + 4)
#define WPAD   (NE + 4)
#define MMAX   8192

typedef unsigned long long ull;

__device__ float g_partials[(size_t)NSPLIT * MMAX * NE];   // 16 MB scratch

__device__ __forceinline__ ull ffma2(ull a, ull b, ull c) {
    ull d;
    asm("fma.rn.f32x2 %0, %1, %2, %3;" : "=l"(d) : "l"(a), "l"(b), "l"(c));
    return d;
}
__device__ __forceinline__ ull pack2(float x) {
    ull d;
    asm("mov.b64 %0, {%1, %2};" : "=l"(d) : "f"(x), "f"(x));
    return d;
}
__device__ __forceinline__ float ullhalf(ull v, int h) {
    return h ? __uint_as_float((unsigned)(v >> 32)) : __uint_as_float((unsigned)v);
}

// ---------------- GEMM with split-K ----------------
__global__ __launch_bounds__(128, 4) void gemm_kernel(
    const float* __restrict__ x, const float* __restrict__ W, int M)
{
    __shared__ float xs[2][KC][XPAD];   // [k][token], transposed
    __shared__ float ws[2][KC][WPAD];   // [k][expert]

    const int tid    = threadIdx.x;
    const int m_base = blockIdx.x * BT;
    const int split  = blockIdx.y;
    const int k0     = split * KSPLIT;

    const int tt = tid & 15;           // token thread  (16)
    const int et = tid >> 4;           // expert thread (8)
    const int m0 = tt * 8;
    const int n0 = et * 8;

    // Coalesced load mapping: 4 lanes cover one row's 16 floats.
    const int xr = tid >> 2;           // 0..31 -> rows xr, xr+32, xr+64, xr+96
    const int xv = (tid & 3) * 4;      // k offset within chunk
    const int wr = tid >> 2;           // 0..31 -> W rows wr, wr+32
    const float* gx = x + (size_t)(m_base + xr) * K_DIM + k0 + xv;
    const float* gw = W + (size_t)wr * K_DIM + k0 + xv;

    ull acc[4][8];
    #pragma unroll
    for (int i = 0; i < 4; i++)
        #pragma unroll
        for (int j = 0; j < 8; j++) acc[i][j] = 0ULL;

    float4 px[4], pw[2];
    // prefetch chunk 0
    #pragma unroll
    for (int j = 0; j < 4; j++) px[j] = *(const float4*)(gx + (size_t)(32 * j) * K_DIM);
    #pragma unroll
    for (int j = 0; j < 2; j++) pw[j] = *(const float4*)(gw + (size_t)(32 * j) * K_DIM);

    // store chunk 0
    #pragma unroll
    for (int j = 0; j < 4; j++) {
        const int r = xr + 32 * j;
        xs[0][xv + 0][r] = px[j].x; xs[0][xv + 1][r] = px[j].y;
        xs[0][xv + 2][r] = px[j].z; xs[0][xv + 3][r] = px[j].w;
    }
    #pragma unroll
    for (int j = 0; j < 2; j++) {
        const int r = wr + 32 * j;
        ws[0][xv + 0][r] = pw[j].x; ws[0][xv + 1][r] = pw[j].y;
        ws[0][xv + 2][r] = pw[j].z; ws[0][xv + 3][r] = pw[j].w;
    }
    __syncthreads();

    int buf = 0;
    #pragma unroll 1
    for (int kb = 0; kb < KSPLIT; kb += KC) {
        const bool has_next = (kb + KC) < KSPLIT;
        if (has_next) {
            const int off = kb + KC;
            #pragma unroll
            for (int j = 0; j < 4; j++) px[j] = *(const float4*)(gx + (size_t)(32 * j) * K_DIM + off);
            #pragma unroll
            for (int j = 0; j < 2; j++) pw[j] = *(const float4*)(gw + (size_t)(32 * j) * K_DIM + off);
        }

        #pragma unroll
        for (int k = 0; k < KC; ++k) {
            const float* xrow = &xs[buf][k][m0];
            ulonglong2 a01 = *(const ulonglong2*)(xrow);       // token pairs (m0,m0+1),(m0+2,m0+3)
            ulonglong2 a23 = *(const ulonglong2*)(xrow + 4);   // (m0+4,m0+5),(m0+6,m0+7)
            float4 b0 = *(const float4*)&ws[buf][k][n0];
            float4 b1 = *(const float4*)&ws[buf][k][n0 + 4];
            ull bb[8];
            bb[0] = pack2(b0.x); bb[1] = pack2(b0.y); bb[2] = pack2(b0.z); bb[3] = pack2(b0.w);
            bb[4] = pack2(b1.x); bb[5] = pack2(b1.y); bb[6] = pack2(b1.z); bb[7] = pack2(b1.w);
            #pragma unroll
            for (int j = 0; j < 8; j++) {
                acc[0][j] = ffma2(a01.x, bb[j], acc[0][j]);
                acc[1][j] = ffma2(a01.y, bb[j], acc[1][j]);
                acc[2][j] = ffma2(a23.x, bb[j], acc[2][j]);
                acc[3][j] = ffma2(a23.y, bb[j], acc[3][j]);
            }
        }

        if (has_next) {
            __syncthreads();
            const int nb = buf ^ 1;
            #pragma unroll
            for (int j = 0; j < 4; j++) {
                const int r = xr + 32 * j;
                xs[nb][xv + 0][r] = px[j].x; xs[nb][xv + 1][r] = px[j].y;
                xs[nb][xv + 2][r] = px[j].z; xs[nb][xv + 3][r] = px[j].w;
            }
            #pragma unroll
            for (int j = 0; j < 2; j++) {
                const int r = wr + 32 * j;
                ws[nb][xv + 0][r] = pw[j].x; ws[nb][xv + 1][r] = pw[j].y;
                ws[nb][xv + 2][r] = pw[j].z; ws[nb][xv + 3][r] = pw[j].w;
            }
            __syncthreads();
            buf = nb;
        }
    }

    // Write partial logits: [split][token][expert]
    #pragma unroll
    for (int i = 0; i < 4; i++) {
        #pragma unroll
        for (int h = 0; h < 2; h++) {
            const int t = m_base + m0 + 2 * i + h;
            float* dst = g_partials + ((size_t)split * M + t) * NE + n0;
            float4 o0 = make_float4(ullhalf(acc[i][0], h), ullhalf(acc[i][1], h),
                                    ullhalf(acc[i][2], h), ullhalf(acc[i][3], h));
            float4 o1 = make_float4(ullhalf(acc[i][4], h), ullhalf(acc[i][5], h),
                                    ullhalf(acc[i][6], h), ullhalf(acc[i][7], h));
            *(float4*)(dst)     = o0;
            *(float4*)(dst + 4) = o1;
        }
    }
}

// ---------------- reduce + softmax + top2 ----------------
__global__ __launch_bounds__(256) void reduce_topk_kernel(
    float* __restrict__ out, int M, int write_idx)
{
    const int warp = threadIdx.x >> 5;
    const int lane = threadIdx.x & 31;
    const int t = blockIdx.x * 8 + warp;
    if (t >= M) return;

    float2 s = make_float2(0.f, 0.f);
    const float* p = g_partials + (size_t)t * NE + 2 * lane;
    #pragma unroll
    for (int si = 0; si < NSPLIT; si++) {
        float2 v = *(const float2*)(p + (size_t)si * M * NE);
        s.x += v.x; s.y += v.y;
    }

    float a1, a2; int i1, i2;
    if (s.x >= s.y) { a1 = s.x; i1 = 2 * lane;     a2 = s.y; i2 = 2 * lane + 1; }
    else            { a1 = s.y; i1 = 2 * lane + 1; a2 = s.x; i2 = 2 * lane;     }

    #pragma unroll
    for (int off = 16; off > 0; off >>= 1) {
        float b1 = __shfl_xor_sync(0xffffffffu, a1, off);
        float b2 = __shfl_xor_sync(0xffffffffu, a2, off);
        int  bi1 = __shfl_xor_sync(0xffffffffu, i1, off);
        int  bi2 = __shfl_xor_sync(0xffffffffu, i2, off);
        if (b1 > a1 || (b1 == a1 && bi1 < i1)) {
            if (b2 > a1 || (b2 == a1 && bi2 < i1)) { a1 = b1; i1 = bi1; a2 = b2; i2 = bi2; }
            else                                   { a2 = a1; i2 = i1;  a1 = b1; i1 = bi1; }
        } else {
            if (b1 > a2 || (b1 == a2 && bi1 < i2)) { a2 = b1; i2 = bi1; }
        }
    }

    // softmax denominator over all 64 (each lane holds 2 raw logits in s)
    float ex = __expf(s.x - a1) + __expf(s.y - a1);
    #pragma unroll
    for (int off = 16; off > 0; off >>= 1)
        ex += __shfl_xor_sync(0xffffffffu, ex, off);

    if (lane == 0) {
        const float inv = 1.0f / ex;
        out[2 * t + 0] = inv;                        // exp(a1-a1)/denom
        out[2 * t + 1] = __expf(a2 - a1) * inv;
        if (write_idx) {
            out[2 * M + 2 * t + 0] = (float)i1;
            out[2 * M + 2 * t + 1] = (float)i2;
        }
    }
}

extern "C" void kernel_launch(void* const* d_in, const int* in_sizes, int n_in,
                              void* d_out, int out_size) {
    const float* x = (const float*)d_in[0];   // (2048,4,4096) -> 8192 x 4096
    const float* W = (const float*)d_in[1];   // (64,4096)
    float* out = (float*)d_out;

    const int M = in_sizes[0] / K_DIM;        // 8192
    const int write_idx = (out_size >= 4 * M) ? 1 : 0;

    dim3 grid(M / BT, NSPLIT);
    gemm_kernel<<<grid, 128>>>(x, W, M);
    reduce_topk_kernel<<<(M + 7) / 8, 256>>>(out, M, write_idx);
}

// round 6
// speedup vs baseline: 2.6096x; 1.4630x over previous
#include <cuda_runtime.h>
#include <stdint.h>

// TopKTokenChoiceRouter: x(8192,4096) fp32 @ W^T(4096,64) -> softmax -> top2.
// Engine: mma.sync.m16n8k8 tf32 with 3xTF32 split (compute_100-safe; tcgen05 is
// 'a'-gated and the harness compiles at compute_100).
// Pipeline: W pre-split (hi/lo tf32) -> split-K(2) GEMM w/ cp.async 4-stage ->
// reduce + softmax + top2.
// Out layout (validated R1/R2): [weights M*2 f32][indices-as-f32 M*2].

#define K_DIM   4096
#define NE      64
#define BM      128
#define BK      32
#define NSPLIT  2
#define KSPLIT  (K_DIM / NSPLIT)      // 2048
#define NCH     (KSPLIT / BK)         // 64 chunks
#define NSTAGE  4
#define MMAX    8192

#define ROWSTR  36                    // padded row stride (floats): conflict-free frags
#define A_BYTES (BM * ROWSTR * 4)     // 18432
#define B_BYTES (NE * ROWSTR * 4)     // 9216
#define STAGE_BYTES (A_BYTES + 2 * B_BYTES)          // 36864
#define OFF_BH  A_BYTES
#define OFF_BL  (A_BYTES + B_BYTES)
#define SMEM_TOTAL (NSTAGE * STAGE_BYTES)            // 147456

typedef unsigned int u32;

__device__ float g_partials[(size_t)NSPLIT * MMAX * NE];  // 4 MB
__device__ u32   g_Whi[NE * K_DIM];                       // 1 MB
__device__ u32   g_Wlo[NE * K_DIM];                       // 1 MB

__device__ __forceinline__ u32 smem_u32(const void* p){
    u32 a; asm("{ .reg .u64 t; cvta.to.shared.u64 t, %1; cvt.u32.u64 %0, t; }" : "=r"(a) : "l"(p));
    return a;
}
__device__ __forceinline__ void split_tf32(float v, u32& hi, u32& lo){
    asm("cvt.rna.tf32.f32 %0, %1;" : "=r"(hi) : "f"(v));
    float r = v - __uint_as_float(hi);
    asm("cvt.rna.tf32.f32 %0, %1;" : "=r"(lo) : "f"(r));
}
__device__ __forceinline__ void cpa16(u32 dst, const void* src){
    asm volatile("cp.async.ca.shared.global [%0], [%1], 16;" :: "r"(dst), "l"(src));
}
__device__ __forceinline__ void cpa_commit(){
    asm volatile("cp.async.commit_group;" ::: "memory");
}
template<int N> __device__ __forceinline__ void cpa_wait(){
    asm volatile("cp.async.wait_group %0;" :: "n"(N) : "memory");
}
__device__ __forceinline__ float lds32(u32 a){
    float v; asm volatile("ld.shared.f32 %0, [%1];" : "=f"(v) : "r"(a));
    return v;
}
__device__ __forceinline__ u32 lds32u(u32 a){
    u32 v; asm volatile("ld.shared.b32 %0, [%1];" : "=r"(v) : "r"(a));
    return v;
}
__device__ __forceinline__ void mma8(float (&d)[4], const u32 (&a)[4], u32 b0, u32 b1){
    asm volatile("mma.sync.aligned.m16n8k8.row.col.f32.tf32.tf32.f32 "
        "{%0,%1,%2,%3}, {%4,%5,%6,%7}, {%8,%9}, {%0,%1,%2,%3};"
        : "+f"(d[0]), "+f"(d[1]), "+f"(d[2]), "+f"(d[3])
        : "r"(a[0]), "r"(a[1]), "r"(a[2]), "r"(a[3]), "r"(b0), "r"(b1));
}

// ---------------- W pre-split ----------------
__global__ __launch_bounds__(256) void conv_w_kernel(const float* __restrict__ W){
    const int gid = blockIdx.x * 256 + threadIdx.x;
    #pragma unroll
    for (int i = 0; i < 4; i++) {
        const int idx = gid + i * 65536;
        u32 hi, lo;
        split_tf32(W[idx], hi, lo);
        g_Whi[idx] = hi;
        g_Wlo[idx] = lo;
    }
}

// ---------------- GEMM (split-K, 3xTF32) ----------------
__global__ __launch_bounds__(256, 1) void gemm_kernel(
    const float* __restrict__ x, int M)
{
    extern __shared__ char smem[];
    const u32 sbase = smem_u32(smem);
    const int tid  = threadIdx.x;
    const int wid  = tid >> 5;
    const int lane = tid & 31;
    const int m_base = blockIdx.x * BM;
    const int split  = blockIdx.y;
    const int k0     = split * KSPLIT;

    // cp.async source/dst mapping
    // A: 1024 float4/stage (128 rows x 8), 4 per thread
    // B hi/lo: 512 float4/stage each, 2 per thread each
    const float* srcA[4]; u32 dstA[4];
    #pragma unroll
    for (int i = 0; i < 4; i++) {
        const int idx = tid + 256 * i;
        const int row = idx >> 3, f4 = idx & 7;
        srcA[i] = x + (size_t)(m_base + row) * K_DIM + k0 + f4 * 4;
        dstA[i] = row * (ROWSTR * 4) + f4 * 16;
    }
    const u32* srcBH[2]; const u32* srcBL[2]; u32 dstB[2];
    #pragma unroll
    for (int i = 0; i < 2; i++) {
        const int idx = tid + 256 * i;
        const int row = idx >> 3, f4 = idx & 7;
        srcBH[i] = g_Whi + (size_t)row * K_DIM + k0 + f4 * 4;
        srcBL[i] = g_Wlo + (size_t)row * K_DIM + k0 + f4 * 4;
        dstB[i] = row * (ROWSTR * 4) + f4 * 16;
    }

    #define ISSUE_STAGE(ch) do {                                            \
        const u32 st = sbase + ((ch) & (NSTAGE - 1)) * STAGE_BYTES;         \
        const int ko = (ch) * BK;                                           \
        _Pragma("unroll")                                                   \
        for (int i = 0; i < 4; i++) cpa16(st + dstA[i], srcA[i] + ko);      \
        _Pragma("unroll")                                                   \
        for (int i = 0; i < 2; i++) cpa16(st + OFF_BH + dstB[i], srcBH[i] + ko); \
        _Pragma("unroll")                                                   \
        for (int i = 0; i < 2; i++) cpa16(st + OFF_BL + dstB[i], srcBL[i] + ko); \
    } while (0)

    // prologue: 3 stages in flight
    ISSUE_STAGE(0); cpa_commit();
    ISSUE_STAGE(1); cpa_commit();
    ISSUE_STAGE(2); cpa_commit();

    float c[8][4];
    #pragma unroll
    for (int n = 0; n < 8; n++)
        #pragma unroll
        for (int j = 0; j < 4; j++) c[n][j] = 0.f;

    const int m0 = wid * 16;
    const u32 aRowOff = (u32)(m0 + (lane >> 2)) * (ROWSTR * 4);
    const u32 aColOff = (u32)(lane & 3) * 4;
    const u32 bNOff   = (u32)(lane >> 2) * (ROWSTR * 4);
    const u32 bKOff   = (u32)(lane & 3) * 4;

    #pragma unroll 1
    for (int ch = 0; ch < NCH; ch++) {
        cpa_wait<2>();
        __syncthreads();

        const u32 st = sbase + (ch & (NSTAGE - 1)) * STAGE_BYTES;
        #pragma unroll
        for (int ks = 0; ks < 4; ks++) {
            const u32 kb = (u32)ks * 32;  // 8 floats = 32 bytes
            // A fragment: load fp32, split to hi/lo
            const u32 aA = st + aRowOff + kb + aColOff;
            float a0 = lds32(aA);
            float a1 = lds32(aA + 8 * ROWSTR * 4);
            float a2 = lds32(aA + 16);
            float a3 = lds32(aA + 8 * ROWSTR * 4 + 16);
            u32 ahi[4], alo[4];
            split_tf32(a0, ahi[0], alo[0]);
            split_tf32(a1, ahi[1], alo[1]);
            split_tf32(a2, ahi[2], alo[2]);
            split_tf32(a3, ahi[3], alo[3]);

            #pragma unroll
            for (int nf = 0; nf < 8; nf++) {
                const u32 bA = st + (u32)nf * (8 * ROWSTR * 4) + bNOff + kb + bKOff;
                const u32 bh0 = lds32u(bA + OFF_BH);
                const u32 bh1 = lds32u(bA + OFF_BH + 16);
                const u32 bl0 = lds32u(bA + OFF_BL);
                const u32 bl1 = lds32u(bA + OFF_BL + 16);
                mma8(c[nf], ahi, bh0, bh1);
                mma8(c[nf], ahi, bl0, bl1);
                mma8(c[nf], alo, bh0, bh1);
            }
        }

        __syncthreads();
        const int cn = ch + 3;
        if (cn < NCH) ISSUE_STAGE(cn);
        cpa_commit();
    }

    // write partial logits [split][token][expert]
    const int t0  = m_base + m0 + (lane >> 2);
    const int col = (lane & 3) * 2;
    #pragma unroll
    for (int nf = 0; nf < 8; nf++) {
        float* p0 = g_partials + ((size_t)split * M + t0) * NE + nf * 8 + col;
        *(float2*)p0            = make_float2(c[nf][0], c[nf][1]);
        *(float2*)(p0 + 8 * NE) = make_float2(c[nf][2], c[nf][3]);
    }
    #undef ISSUE_STAGE
}

// ---------------- reduce + softmax + top2 ----------------
__global__ __launch_bounds__(256) void reduce_topk_kernel(
    float* __restrict__ out, int M, int write_idx)
{
    const int warp = threadIdx.x >> 5;
    const int lane = threadIdx.x & 31;
    const int t = blockIdx.x * 8 + warp;
    if (t >= M) return;

    float2 s = make_float2(0.f, 0.f);
    const float* p = g_partials + (size_t)t * NE + 2 * lane;
    #pragma unroll
    for (int si = 0; si < NSPLIT; si++) {
        float2 v = *(const float2*)(p + (size_t)si * M * NE);
        s.x += v.x; s.y += v.y;
    }

    float a1, a2; int i1, i2;
    if (s.x >= s.y) { a1 = s.x; i1 = 2 * lane;     a2 = s.y; i2 = 2 * lane + 1; }
    else            { a1 = s.y; i1 = 2 * lane + 1; a2 = s.x; i2 = 2 * lane;     }

    #pragma unroll
    for (int off = 16; off > 0; off >>= 1) {
        float b1 = __shfl_xor_sync(0xffffffffu, a1, off);
        float b2 = __shfl_xor_sync(0xffffffffu, a2, off);
        int  bi1 = __shfl_xor_sync(0xffffffffu, i1, off);
        int  bi2 = __shfl_xor_sync(0xffffffffu, i2, off);
        if (b1 > a1 || (b1 == a1 && bi1 < i1)) {
            if (b2 > a1 || (b2 == a1 && bi2 < i1)) { a1 = b1; i1 = bi1; a2 = b2; i2 = bi2; }
            else                                   { a2 = a1; i2 = i1;  a1 = b1; i1 = bi1; }
        } else {
            if (b1 > a2 || (b1 == a2 && bi1 < i2)) { a2 = b1; i2 = bi1; }
        }
    }

    float ex = __expf(s.x - a1) + __expf(s.y - a1);
    #pragma unroll
    for (int off = 16; off > 0; off >>= 1)
        ex += __shfl_xor_sync(0xffffffffu, ex, off);

    if (lane == 0) {
        const float inv = 1.0f / ex;
        out[2 * t + 0] = inv;
        out[2 * t + 1] = __expf(a2 - a1) * inv;
        if (write_idx) {
            out[2 * M + 2 * t + 0] = (float)i1;
            out[2 * M + 2 * t + 1] = (float)i2;
        }
    }
}

extern "C" void kernel_launch(void* const* d_in, const int* in_sizes, int n_in,
                              void* d_out, int out_size) {
    const float* x = (const float*)d_in[0];   // 8192 x 4096 fp32
    const float* W = (const float*)d_in[1];   // 64 x 4096 fp32
    float* out = (float*)d_out;

    const int M = in_sizes[0] / K_DIM;        // 8192
    const int write_idx = (out_size >= 4 * M) ? 1 : 0;

    cudaFuncSetAttribute(gemm_kernel,
                         cudaFuncAttributeMaxDynamicSharedMemorySize, SMEM_TOTAL);

    conv_w_kernel<<<256, 256>>>(W);
    dim3 grid(M / BM, NSPLIT);
    gemm_kernel<<<grid, 256, SMEM_TOTAL>>>(x, M);
    reduce_topk_kernel<<<(M + 7) / 8, 256>>>(out, M, write_idx);
}